// round 15
// baseline (speedup 1.0000x reference)
#include <cuda_runtime.h>

#define N_NODES 100000
#define N_EDGES 1600000
#define H0 256
#define H1 1024
#define IN_DIM 64

// Scratch (no allocations allowed)
__device__ float g_h1[H1];
__device__ float g_x[N_NODES];     // raw relu(FC2) output
__device__ float g_deg[N_NODES];   // degree (incl. self loop)
__device__ float g_dinv[N_NODES];  // deg^-1/2
__device__ float g_xd[N_NODES];    // gcn_w * x[i] * dinv[i]

__device__ __forceinline__ float warp_sum(float s) {
#pragma unroll
    for (int o = 16; o; o >>= 1) s += __shfl_xor_sync(0xffffffffu, s, o);
    return s;
}

// ---------------------------------------------------------------------------
// L1: single wave of 128 blocks. Every block: float4 deg-init slice,
// FC0 (redundant per block, W0 L2-hot), then its FC1 slice (warp-per-row).
// ---------------------------------------------------------------------------
__global__ void k1_fc01_deginit(const float* __restrict__ emb,
                                const float* __restrict__ W0,
                                const float* __restrict__ b0,
                                const float* __restrict__ W1,
                                const float* __restrict__ b1) {
    int t = threadIdx.x;
    int gi = blockIdx.x * blockDim.x + t;   // 0..32767
    if (gi < N_NODES / 4)
        reinterpret_cast<float4*>(g_deg)[gi] = make_float4(1.f, 1.f, 1.f, 1.f);

    __shared__ float se[IN_DIM];
    __shared__ float sh0[H0];
    if (t < IN_DIM) se[t] = emb[t];
    __syncthreads();

    // FC0: one row per thread (blockDim == 256 == H0)
    {
        const float4* w = reinterpret_cast<const float4*>(W0 + (size_t)t * IN_DIM);
        const float4* h = reinterpret_cast<const float4*>(se);
        float s = 0.f;
#pragma unroll
        for (int i = 0; i < IN_DIM / 4; i++) {
            float4 wv = w[i];
            float4 hv = h[i];
            s += wv.x * hv.x + wv.y * hv.y + wv.z * hv.z + wv.w * hv.w;
        }
        sh0[t] = fmaxf(s + b0[t], 0.f);
    }
    __syncthreads();

    // FC1: warp-per-row, 8 rows per block (128 blocks x 8 = 1024 rows)
    int row  = blockIdx.x * 8 + (t >> 5);
    int lane = t & 31;
    const float4* w = reinterpret_cast<const float4*>(W1 + (size_t)row * H0);
    const float4* h = reinterpret_cast<const float4*>(sh0);
    float s = 0.f;
#pragma unroll
    for (int i = lane; i < H0 / 4; i += 32) {
        float4 wv = w[i];
        float4 hv = h[i];
        s += wv.x * hv.x + wv.y * hv.y + wv.z * hv.z + wv.w * hv.w;
    }
    s = warp_sum(s);
    if (lane == 0) g_h1[row] = fmaxf(s + b1[row], 0.f);
}

// ---------------------------------------------------------------------------
// L3 (dominant): PERSISTENT FC2 GEMV [1024]->[100000] + ReLU + fused
// degree-count. 1184 blocks grid-stride over row-groups of 8 (one per warp);
// each iteration also fires a 256-edge degcount slice so the REDs stay
// interleaved with the W2 DRAM stream (not front-loaded).
// Edge slice id = iter*1184 + bid covers 0..6249 within iters 0..5; every
// block executes >= 10 iterations, so coverage is complete.
// ---------------------------------------------------------------------------
#define K3_BLOCKS 1184  // 148 * 8
__global__ void __launch_bounds__(256)
k3_fc2_degcount(const float* __restrict__ W2,
                const float* __restrict__ b2,
                const int*   __restrict__ dst) {
    int t    = threadIdx.x;
    int lane = t & 31;
    const float4* h = reinterpret_cast<const float4*>(g_h1);

    int iter = 0;
    for (int row0 = blockIdx.x * 8; row0 < N_NODES;
         row0 += K3_BLOCKS * 8, iter++) {
        // interleaved degree-count slice
        int e = (iter * K3_BLOCKS + blockIdx.x) * 256 + t;
        if (e < N_EDGES) atomicAdd(&g_deg[dst[e]], 1.0f);

        int row = row0 + (t >> 5);
        if (row < N_NODES) {
            const float4* w = reinterpret_cast<const float4*>(W2 + (size_t)row * H1);
            float s = 0.f;
#pragma unroll
            for (int i = lane; i < H1 / 4; i += 32) {  // 8 float4 per lane
                float4 wv = __ldcs(&w[i]);             // read-once weights
                float4 hv = __ldg(&h[i]);              // L1-resident broadcast
                s += wv.x * hv.x + wv.y * hv.y + wv.z * hv.z + wv.w * hv.w;
            }
            s = warp_sum(s);
            if (lane == 0) g_x[row] = fmaxf(s + b2[row], 0.f);
        }
    }
}

// ---------------------------------------------------------------------------
// L3b: node epilogue, float4-vectorized (4 nodes/thread):
//   dinv = rsqrt(deg); xd = gcn_w * x * dinv; out = xd (self-loop term)
// ---------------------------------------------------------------------------
__global__ void k3b_nodeprep(const float* __restrict__ gw,
                             float* __restrict__ out) {
    int i4 = blockIdx.x * blockDim.x + threadIdx.x;
    if (i4 * 4 >= N_NODES) return;  // N_NODES % 4 == 0
    float g = __ldg(gw);
    float4 d = reinterpret_cast<const float4*>(g_deg)[i4];
    float4 x = reinterpret_cast<const float4*>(g_x)[i4];
    float4 di, xd;
    di.x = rsqrtf(d.x); di.y = rsqrtf(d.y);
    di.z = rsqrtf(d.z); di.w = rsqrtf(d.w);
    xd.x = g * x.x * di.x; xd.y = g * x.y * di.y;
    xd.z = g * x.z * di.z; xd.w = g * x.w * di.w;
    reinterpret_cast<float4*>(g_dinv)[i4] = di;
    reinterpret_cast<float4*>(g_xd)[i4]   = xd;
    reinterpret_cast<float4*>(out)[i4]    = xd;
}

// ---------------------------------------------------------------------------
// L4: edge scatter (structurally floor-bound at ~19us; frozen at best form).
// 4 edges/thread grid-stride, all 303k threads busy, 8 resident blocks/SM.
//   out[dst] += g_xd[src]
// ---------------------------------------------------------------------------
#define K4_BLOCKS 1184  // 148 * 8
__global__ void __launch_bounds__(256, 8)
k4_scatter(const int* __restrict__ src,
           const int* __restrict__ dst,
           float* __restrict__ out) {
    const int4* sp = reinterpret_cast<const int4*>(src);
    const int4* dp = reinterpret_cast<const int4*>(dst);
    const int n_groups = N_EDGES / 4;  // 400000
    const int stride = K4_BLOCKS * 256;

    for (int g = blockIdx.x * 256 + threadIdx.x; g < n_groups; g += stride) {
        int4 s4 = sp[g];
        int4 d4 = dp[g];
        float v0 = __ldg(&g_xd[s4.x]);
        float v1 = __ldg(&g_xd[s4.y]);
        float v2 = __ldg(&g_xd[s4.z]);
        float v3 = __ldg(&g_xd[s4.w]);
        atomicAdd(&out[d4.x], v0);
        atomicAdd(&out[d4.y], v1);
        atomicAdd(&out[d4.z], v2);
        atomicAdd(&out[d4.w], v3);
    }
}

// ---------------------------------------------------------------------------
// L5: final normalization (float4): out[i] = gcn_b + dinv[i] * out[i]
// ---------------------------------------------------------------------------
__global__ void k5_finalize(float* __restrict__ out,
                            const float* __restrict__ gb) {
    int i4 = blockIdx.x * blockDim.x + threadIdx.x;
    if (i4 * 4 >= N_NODES) return;
    float b = __ldg(gb);
    float4 di = reinterpret_cast<const float4*>(g_dinv)[i4];
    float4 o  = reinterpret_cast<const float4*>(out)[i4];
    o.x = b + di.x * o.x;
    o.y = b + di.y * o.y;
    o.z = b + di.z * o.z;
    o.w = b + di.w * o.w;
    reinterpret_cast<float4*>(out)[i4] = o;
}

// ---------------------------------------------------------------------------
extern "C" void kernel_launch(void* const* d_in, const int* in_sizes, int n_in,
                              void* d_out, int out_size) {
    const float* emb = (const float*)d_in[0];
    const int*   ei  = (const int*)d_in[1];  // [2, E] int32 (JAX x64 off)
    const float* W0  = (const float*)d_in[2];
    const float* b0  = (const float*)d_in[3];
    const float* W1  = (const float*)d_in[4];
    const float* b1  = (const float*)d_in[5];
    const float* W2  = (const float*)d_in[6];
    const float* b2  = (const float*)d_in[7];
    const float* gw  = (const float*)d_in[8];
    const float* gb  = (const float*)d_in[9];
    float*       out = (float*)d_out;

    const int* src = ei;            // row 0
    const int* dst = ei + N_EDGES;  // row 1

    const int NODE4_BLOCKS = (N_NODES / 4 + 255) / 256;  // 98

    k1_fc01_deginit<<<H1 / 8, 256>>>(emb, W0, b0, W1, b1);   // 128 blocks
    k3_fc2_degcount<<<K3_BLOCKS, 256>>>(W2, b2, dst);
    k3b_nodeprep<<<NODE4_BLOCKS, 256>>>(gw, out);
    k4_scatter<<<K4_BLOCKS, 256>>>(src, dst, out);
    k5_finalize<<<NODE4_BLOCKS, 256>>>(out, gb);
}

// round 16
// speedup vs baseline: 1.0451x; 1.0451x over previous
#include <cuda_runtime.h>

#define N_NODES 100000
#define N_EDGES 1600000
#define H0 256
#define H1 1024
#define IN_DIM 64

// Scratch (no allocations allowed)
__device__ float g_h1[H1];
__device__ float g_x[N_NODES];     // raw relu(FC2) output
__device__ float g_deg[N_NODES];   // degree (incl. self loop)
__device__ float g_dinv[N_NODES];  // deg^-1/2
__device__ float g_xd[N_NODES];    // gcn_w * x[i] * dinv[i]

__device__ __forceinline__ float warp_sum(float s) {
#pragma unroll
    for (int o = 16; o; o >>= 1) s += __shfl_xor_sync(0xffffffffu, s, o);
    return s;
}

// ---------------------------------------------------------------------------
// L1: single wave of 128 blocks. Every block: float4 deg-init slice,
// FC0 (redundant per block, W0 L2-hot), then its FC1 slice (warp-per-row).
// ---------------------------------------------------------------------------
__global__ void k1_fc01_deginit(const float* __restrict__ emb,
                                const float* __restrict__ W0,
                                const float* __restrict__ b0,
                                const float* __restrict__ W1,
                                const float* __restrict__ b1) {
    int t = threadIdx.x;
    int gi = blockIdx.x * blockDim.x + t;   // 0..32767
    if (gi < N_NODES / 4)
        reinterpret_cast<float4*>(g_deg)[gi] = make_float4(1.f, 1.f, 1.f, 1.f);

    __shared__ float se[IN_DIM];
    __shared__ float sh0[H0];
    if (t < IN_DIM) se[t] = emb[t];
    __syncthreads();

    // FC0: one row per thread (blockDim == 256 == H0)
    {
        const float4* w = reinterpret_cast<const float4*>(W0 + (size_t)t * IN_DIM);
        const float4* h = reinterpret_cast<const float4*>(se);
        float s = 0.f;
#pragma unroll
        for (int i = 0; i < IN_DIM / 4; i++) {
            float4 wv = w[i];
            float4 hv = h[i];
            s += wv.x * hv.x + wv.y * hv.y + wv.z * hv.z + wv.w * hv.w;
        }
        sh0[t] = fmaxf(s + b0[t], 0.f);
    }
    __syncthreads();

    // FC1: warp-per-row, 8 rows per block (128 blocks x 8 = 1024 rows)
    int row  = blockIdx.x * 8 + (t >> 5);
    int lane = t & 31;
    const float4* w = reinterpret_cast<const float4*>(W1 + (size_t)row * H0);
    const float4* h = reinterpret_cast<const float4*>(sh0);
    float s = 0.f;
#pragma unroll
    for (int i = lane; i < H0 / 4; i += 32) {
        float4 wv = w[i];
        float4 hv = h[i];
        s += wv.x * hv.x + wv.y * hv.y + wv.z * hv.z + wv.w * hv.w;
    }
    s = warp_sum(s);
    if (lane == 0) g_h1[row] = fmaxf(s + b1[row], 0.f);
}

// ---------------------------------------------------------------------------
// L3 (dominant): FC2 GEMV [1024]->[100000] + ReLU, TWO rows per warp for
// doubled per-lane MLP (16 outstanding float4 loads, 2 independent FFMA
// chains). 6250 blocks x 16 rows, sequential CTA->W2 mapping preserved
// (the R15 persistent variant broke streaming locality and regressed).
// Fused degree-count: 256 edges/block; 6250*256 = 1.6M edges exactly.
// ---------------------------------------------------------------------------
__global__ void k3_fc2_degcount(const float* __restrict__ W2,
                                const float* __restrict__ b2,
                                const int*   __restrict__ dst) {
    int t = threadIdx.x;

    // degree-count slice (coalesced, fire-and-forget, rides in W2 shadow)
    {
        int e = blockIdx.x * 256 + t;  // < 6250*256 == N_EDGES
        atomicAdd(&g_deg[dst[e]], 1.0f);
    }

    int lane = t & 31;
    int rowA = blockIdx.x * 16 + (t >> 5) * 2;  // two adjacent rows per warp
    int rowB = rowA + 1;
    if (rowA >= N_NODES) return;

    const float4* h  = reinterpret_cast<const float4*>(g_h1);
    const float4* wA = reinterpret_cast<const float4*>(W2 + (size_t)rowA * H1);
    const float4* wB = reinterpret_cast<const float4*>(W2 + (size_t)rowB * H1);
    float sA = 0.f, sB = 0.f;
#pragma unroll
    for (int i = lane; i < H1 / 4; i += 32) {  // 8 float4 per lane per row
        float4 hv = __ldg(&h[i]);              // L1-resident broadcast
        float4 a  = __ldcs(&wA[i]);            // read-once weights
        float4 b  = __ldcs(&wB[i]);
        sA += a.x * hv.x + a.y * hv.y + a.z * hv.z + a.w * hv.w;
        sB += b.x * hv.x + b.y * hv.y + b.z * hv.z + b.w * hv.w;
    }
    sA = warp_sum(sA);
    sB = warp_sum(sB);
    if (lane == 0) {
        g_x[rowA] = fmaxf(sA + b2[rowA], 0.f);
        if (rowB < N_NODES) g_x[rowB] = fmaxf(sB + b2[rowB], 0.f);
    }
}

// ---------------------------------------------------------------------------
// L3b: node epilogue, float4-vectorized (4 nodes/thread):
//   dinv = rsqrt(deg); xd = gcn_w * x * dinv; out = xd (self-loop term)
// ---------------------------------------------------------------------------
__global__ void k3b_nodeprep(const float* __restrict__ gw,
                             float* __restrict__ out) {
    int i4 = blockIdx.x * blockDim.x + threadIdx.x;
    if (i4 * 4 >= N_NODES) return;  // N_NODES % 4 == 0
    float g = __ldg(gw);
    float4 d = reinterpret_cast<const float4*>(g_deg)[i4];
    float4 x = reinterpret_cast<const float4*>(g_x)[i4];
    float4 di, xd;
    di.x = rsqrtf(d.x); di.y = rsqrtf(d.y);
    di.z = rsqrtf(d.z); di.w = rsqrtf(d.w);
    xd.x = g * x.x * di.x; xd.y = g * x.y * di.y;
    xd.z = g * x.z * di.z; xd.w = g * x.w * di.w;
    reinterpret_cast<float4*>(g_dinv)[i4] = di;
    reinterpret_cast<float4*>(g_xd)[i4]   = xd;
    reinterpret_cast<float4*>(out)[i4]    = xd;
}

// ---------------------------------------------------------------------------
// L4: edge scatter (structurally floor-bound at ~19us; frozen at best form).
// 4 edges/thread grid-stride, all 303k threads busy, 8 resident blocks/SM.
//   out[dst] += g_xd[src]
// ---------------------------------------------------------------------------
#define K4_BLOCKS 1184  // 148 * 8
__global__ void __launch_bounds__(256, 8)
k4_scatter(const int* __restrict__ src,
           const int* __restrict__ dst,
           float* __restrict__ out) {
    const int4* sp = reinterpret_cast<const int4*>(src);
    const int4* dp = reinterpret_cast<const int4*>(dst);
    const int n_groups = N_EDGES / 4;  // 400000
    const int stride = K4_BLOCKS * 256;

    for (int g = blockIdx.x * 256 + threadIdx.x; g < n_groups; g += stride) {
        int4 s4 = sp[g];
        int4 d4 = dp[g];
        float v0 = __ldg(&g_xd[s4.x]);
        float v1 = __ldg(&g_xd[s4.y]);
        float v2 = __ldg(&g_xd[s4.z]);
        float v3 = __ldg(&g_xd[s4.w]);
        atomicAdd(&out[d4.x], v0);
        atomicAdd(&out[d4.y], v1);
        atomicAdd(&out[d4.z], v2);
        atomicAdd(&out[d4.w], v3);
    }
}

// ---------------------------------------------------------------------------
// L5: final normalization (float4): out[i] = gcn_b + dinv[i] * out[i]
// ---------------------------------------------------------------------------
__global__ void k5_finalize(float* __restrict__ out,
                            const float* __restrict__ gb) {
    int i4 = blockIdx.x * blockDim.x + threadIdx.x;
    if (i4 * 4 >= N_NODES) return;
    float b = __ldg(gb);
    float4 di = reinterpret_cast<const float4*>(g_dinv)[i4];
    float4 o  = reinterpret_cast<const float4*>(out)[i4];
    o.x = b + di.x * o.x;
    o.y = b + di.y * o.y;
    o.z = b + di.z * o.z;
    o.w = b + di.w * o.w;
    reinterpret_cast<float4*>(out)[i4] = o;
}

// ---------------------------------------------------------------------------
extern "C" void kernel_launch(void* const* d_in, const int* in_sizes, int n_in,
                              void* d_out, int out_size) {
    const float* emb = (const float*)d_in[0];
    const int*   ei  = (const int*)d_in[1];  // [2, E] int32 (JAX x64 off)
    const float* W0  = (const float*)d_in[2];
    const float* b0  = (const float*)d_in[3];
    const float* W1  = (const float*)d_in[4];
    const float* b1  = (const float*)d_in[5];
    const float* W2  = (const float*)d_in[6];
    const float* b2  = (const float*)d_in[7];
    const float* gw  = (const float*)d_in[8];
    const float* gb  = (const float*)d_in[9];
    float*       out = (float*)d_out;

    const int* src = ei;            // row 0
    const int* dst = ei + N_EDGES;  // row 1

    const int NODE4_BLOCKS = (N_NODES / 4 + 255) / 256;  // 98
    const int K3_GRID = (N_NODES + 15) / 16;             // 6250

    k1_fc01_deginit<<<H1 / 8, 256>>>(emb, W0, b0, W1, b1);   // 128 blocks
    k3_fc2_degcount<<<K3_GRID, 256>>>(W2, b2, dst);
    k3b_nodeprep<<<NODE4_BLOCKS, 256>>>(gw, out);
    k4_scatter<<<K4_BLOCKS, 256>>>(src, dst, out);
    k5_finalize<<<NODE4_BLOCKS, 256>>>(out, gb);
}

// round 17
// speedup vs baseline: 1.0678x; 1.0218x over previous
#include <cuda_runtime.h>

#define N_NODES 100000
#define N_EDGES 1600000
#define H0 256
#define H1 1024
#define IN_DIM 64

// Scratch (no allocations allowed)
__device__ float g_h1[H1];
__device__ float g_x[N_NODES];     // raw relu(FC2) output
__device__ float g_deg[N_NODES];   // degree (incl. self loop)
__device__ float g_dinv[N_NODES];  // deg^-1/2
__device__ float g_xd[N_NODES];    // gcn_w * x[i] * dinv[i]

__device__ __forceinline__ float warp_sum(float s) {
#pragma unroll
    for (int o = 16; o; o >>= 1) s += __shfl_xor_sync(0xffffffffu, s, o);
    return s;
}

// ---------------------------------------------------------------------------
// L1: single wave of 128 blocks. Every block: float4 deg-init slice
// (25000 float4 over 32768 threads), FC0 (redundant per block, W0 L2-hot),
// then its FC1 slice (warp-per-row, 8 rows/block).
// ---------------------------------------------------------------------------
__global__ void k1_fc01_deginit(const float* __restrict__ emb,
                                const float* __restrict__ W0,
                                const float* __restrict__ b0,
                                const float* __restrict__ W1,
                                const float* __restrict__ b1) {
    int t = threadIdx.x;
    int gi = blockIdx.x * blockDim.x + t;   // 0..32767
    if (gi < N_NODES / 4)
        reinterpret_cast<float4*>(g_deg)[gi] = make_float4(1.f, 1.f, 1.f, 1.f);

    __shared__ float se[IN_DIM];
    __shared__ float sh0[H0];
    if (t < IN_DIM) se[t] = emb[t];
    __syncthreads();

    // FC0: one row per thread (blockDim == 256 == H0)
    {
        const float4* w = reinterpret_cast<const float4*>(W0 + (size_t)t * IN_DIM);
        const float4* h = reinterpret_cast<const float4*>(se);
        float s = 0.f;
#pragma unroll
        for (int i = 0; i < IN_DIM / 4; i++) {
            float4 wv = w[i];
            float4 hv = h[i];
            s += wv.x * hv.x + wv.y * hv.y + wv.z * hv.z + wv.w * hv.w;
        }
        sh0[t] = fmaxf(s + b0[t], 0.f);
    }
    __syncthreads();

    // FC1: warp-per-row, 8 rows per block (128 blocks x 8 = 1024 rows)
    int row  = blockIdx.x * 8 + (t >> 5);
    int lane = t & 31;
    const float4* w = reinterpret_cast<const float4*>(W1 + (size_t)row * H0);
    const float4* h = reinterpret_cast<const float4*>(sh0);
    float s = 0.f;
#pragma unroll
    for (int i = lane; i < H0 / 4; i += 32) {
        float4 wv = w[i];
        float4 hv = h[i];
        s += wv.x * hv.x + wv.y * hv.y + wv.z * hv.z + wv.w * hv.w;
    }
    s = warp_sum(s);
    if (lane == 0) g_h1[row] = fmaxf(s + b1[row], 0.f);
}

// ---------------------------------------------------------------------------
// L3 (dominant): FC2 GEMV [1024]->[100000] + ReLU, plus a fused degree-count
// slice (128 edges/block, fire-and-forget REDs riding in the W2 DRAM shadow).
// Warp-per-row, 12500 sequential blocks = best measured streaming pattern
// (persistent grid and 2-row/warp variants both regressed). h1 read directly
// from global (4KB, L1-broadcast-resident): no smem staging, no barrier.
// ---------------------------------------------------------------------------
__global__ void k3_fc2_degcount(const float* __restrict__ W2,
                                const float* __restrict__ b2,
                                const int*   __restrict__ dst) {
    int t = threadIdx.x;

    if (t < 128) {
        int e = blockIdx.x * 128 + t;  // e < 12500*128 == N_EDGES
        atomicAdd(&g_deg[dst[e]], 1.0f);
    }

    int row  = blockIdx.x * 8 + (t >> 5);
    int lane = t & 31;
    if (row >= N_NODES) return;

    const float4* w = reinterpret_cast<const float4*>(W2 + (size_t)row * H1);
    const float4* h = reinterpret_cast<const float4*>(g_h1);
    float s = 0.f;
#pragma unroll
    for (int i = lane; i < H1 / 4; i += 32) {  // 8 float4 per lane
        float4 wv = __ldcs(&w[i]);             // streaming: read-once weights
        float4 hv = __ldg(&h[i]);              // L1-resident broadcast
        s += wv.x * hv.x + wv.y * hv.y + wv.z * hv.z + wv.w * hv.w;
    }
    s = warp_sum(s);
    if (lane == 0) g_x[row] = fmaxf(s + b2[row], 0.f);
}

// ---------------------------------------------------------------------------
// L3b: node epilogue, float4-vectorized (4 nodes/thread):
//   dinv = rsqrt(deg); xd = gcn_w * x * dinv; out = xd (self-loop term)
// ---------------------------------------------------------------------------
__global__ void k3b_nodeprep(const float* __restrict__ gw,
                             float* __restrict__ out) {
    int i4 = blockIdx.x * blockDim.x + threadIdx.x;
    if (i4 * 4 >= N_NODES) return;  // N_NODES % 4 == 0
    float g = __ldg(gw);
    float4 d = reinterpret_cast<const float4*>(g_deg)[i4];
    float4 x = reinterpret_cast<const float4*>(g_x)[i4];
    float4 di, xd;
    di.x = rsqrtf(d.x); di.y = rsqrtf(d.y);
    di.z = rsqrtf(d.z); di.w = rsqrtf(d.w);
    xd.x = g * x.x * di.x; xd.y = g * x.y * di.y;
    xd.z = g * x.z * di.z; xd.w = g * x.w * di.w;
    reinterpret_cast<float4*>(g_dinv)[i4] = di;
    reinterpret_cast<float4*>(g_xd)[i4]   = xd;
    reinterpret_cast<float4*>(out)[i4]    = xd;
}

// ---------------------------------------------------------------------------
// L4: edge scatter (structurally floor-bound at ~19us across 6 variants).
// 4 edges/thread grid-stride, all 303k threads busy, 8 resident blocks/SM.
//   out[dst] += g_xd[src]
// ---------------------------------------------------------------------------
#define K4_BLOCKS 1184  // 148 * 8
__global__ void __launch_bounds__(256, 8)
k4_scatter(const int* __restrict__ src,
           const int* __restrict__ dst,
           float* __restrict__ out) {
    const int4* sp = reinterpret_cast<const int4*>(src);
    const int4* dp = reinterpret_cast<const int4*>(dst);
    const int n_groups = N_EDGES / 4;  // 400000
    const int stride = K4_BLOCKS * 256;

    for (int g = blockIdx.x * 256 + threadIdx.x; g < n_groups; g += stride) {
        int4 s4 = sp[g];
        int4 d4 = dp[g];
        float v0 = __ldg(&g_xd[s4.x]);
        float v1 = __ldg(&g_xd[s4.y]);
        float v2 = __ldg(&g_xd[s4.z]);
        float v3 = __ldg(&g_xd[s4.w]);
        atomicAdd(&out[d4.x], v0);
        atomicAdd(&out[d4.y], v1);
        atomicAdd(&out[d4.z], v2);
        atomicAdd(&out[d4.w], v3);
    }
}

// ---------------------------------------------------------------------------
// L5: final normalization (float4): out[i] = gcn_b + dinv[i] * out[i]
// ---------------------------------------------------------------------------
__global__ void k5_finalize(float* __restrict__ out,
                            const float* __restrict__ gb) {
    int i4 = blockIdx.x * blockDim.x + threadIdx.x;
    if (i4 * 4 >= N_NODES) return;
    float b = __ldg(gb);
    float4 di = reinterpret_cast<const float4*>(g_dinv)[i4];
    float4 o  = reinterpret_cast<const float4*>(out)[i4];
    o.x = b + di.x * o.x;
    o.y = b + di.y * o.y;
    o.z = b + di.z * o.z;
    o.w = b + di.w * o.w;
    reinterpret_cast<float4*>(out)[i4] = o;
}

// ---------------------------------------------------------------------------
extern "C" void kernel_launch(void* const* d_in, const int* in_sizes, int n_in,
                              void* d_out, int out_size) {
    const float* emb = (const float*)d_in[0];
    const int*   ei  = (const int*)d_in[1];  // [2, E] int32 (JAX x64 off)
    const float* W0  = (const float*)d_in[2];
    const float* b0  = (const float*)d_in[3];
    const float* W1  = (const float*)d_in[4];
    const float* b1  = (const float*)d_in[5];
    const float* W2  = (const float*)d_in[6];
    const float* b2  = (const float*)d_in[7];
    const float* gw  = (const float*)d_in[8];
    const float* gb  = (const float*)d_in[9];
    float*       out = (float*)d_out;

    const int* src = ei;            // row 0
    const int* dst = ei + N_EDGES;  // row 1

    const int NODE4_BLOCKS = (N_NODES / 4 + 255) / 256;  // 98

    k1_fc01_deginit<<<H1 / 8, 256>>>(emb, W0, b0, W1, b1);   // 128 blocks
    k3_fc2_degcount<<<(N_NODES + 7) / 8, 256>>>(W2, b2, dst);
    k3b_nodeprep<<<NODE4_BLOCKS, 256>>>(gw, out);
    k4_scatter<<<K4_BLOCKS, 256>>>(src, dst, out);
    k5_finalize<<<NODE4_BLOCKS, 256>>>(out, gb);
}